// round 14
// baseline (speedup 1.0000x reference)
#include <cuda_runtime.h>
#include <cuda_bf16.h>

#define H_OUT 228
#define W_OUT 304
#define S_RAS 304
#define N_V   8192
#define M_F   2048
#define NSEG  2
#define MSEG  (M_F / NSEG)        // 1024 faces per segment, one smem pass
#define TILE_W 32
#define TILE_H 8
#define TILES_X 10                // ceil(304/32)
#define TILES_Y 29                // ceil(228/8)
#define NTHR   256                // 1 px per thread
#define NPIX  (H_OUT * W_OUT)     // 69312 (divisible by 4)
#define FAR_V 100.0f
#define EPS_V 1e-7f
#define CULL_EPS 1e-4f

// scratch (no allocations allowed)
__device__ float4 g_vt[N_V];              // per-vertex (X, Y, 1/z, 0)
__device__ float4 g_p[M_F];               // (A0, A1, B0, B1)  -- pair-packed for f32x2
__device__ float4 g_q[M_F];               // (C0, C1, Az, Bz)
__device__ float  g_r[M_F];               // Cz
__device__ float4 g_bb[M_F];              // (xmin, xmax, ymin, ymax); NaN if degenerate
__device__ float  g_pm[NSEG * NPIX];      // per-segment max inv_z (every slot written)

__device__ __forceinline__ void pdl_wait() {
    asm volatile("griddepcontrol.wait;" ::: "memory");
}
__device__ __forceinline__ unsigned long long packf2(float lo, float hi) {
    unsigned long long r;
    asm("mov.b64 %0, {%1,%2};" : "=l"(r) : "f"(lo), "f"(hi));
    return r;
}
__device__ __forceinline__ unsigned long long fma2(unsigned long long a,
                                                   unsigned long long b,
                                                   unsigned long long c) {
    unsigned long long d;
    asm("fma.rn.f32x2 %0, %1, %2, %3;" : "=l"(d) : "l"(a), "l"(b), "l"(c));
    return d;
}
__device__ __forceinline__ void unpackf2(unsigned long long v, float& lo, float& hi) {
    asm("mov.b64 {%0,%1}, %2;" : "=f"(lo), "=f"(hi) : "l"(v));
}

static void launch_pdl(void* fn, dim3 grid, dim3 block, void** args) {
    cudaLaunchAttribute attr[1];
    attr[0].id = cudaLaunchAttributeProgrammaticStreamSerialization;
    attr[0].val.programmaticStreamSerializationAllowed = 1;
    cudaLaunchConfig_t cfg = {};
    cfg.gridDim = grid; cfg.blockDim = block;
    cfg.attrs = attr; cfg.numAttrs = 1;
    cudaLaunchKernelExC(&cfg, fn, args);
}

// ---------------------------------------------------------------------------
// 1a) per-vertex transform: coalesced loads, short chain
// ---------------------------------------------------------------------------
__global__ void __launch_bounds__(128) vert_kernel(const float* __restrict__ verts,
                                                   const float* __restrict__ Km,
                                                   const float* __restrict__ Rm,
                                                   const float* __restrict__ tm)
{
    int i = blockIdx.x * blockDim.x + threadIdx.x;
    if (i >= N_V) return;

    float u  = verts[3 * i + 0];
    float vv = verts[3 * i + 1];
    float d  = verts[3 * i + 2];

    float k0 = Km[0], k1 = Km[1], k2 = Km[2];
    float k3 = Km[3], k4 = Km[4], k5 = Km[5];
    float k6 = Km[6], k7 = Km[7], k8 = Km[8];

    // adjugate inverse of K
    float c00 = k4 * k8 - k5 * k7;
    float c01 = k5 * k6 - k3 * k8;
    float c02 = k3 * k7 - k4 * k6;
    float det = k0 * c00 + k1 * c01 + k2 * c02;
    float id  = __fdividef(1.0f, det);
    float i00 = c00 * id, i01 = (k2 * k7 - k1 * k8) * id, i02 = (k1 * k5 - k2 * k4) * id;
    float i10 = c01 * id, i11 = (k0 * k8 - k2 * k6) * id, i12 = (k2 * k3 - k0 * k5) * id;
    float i20 = c02 * id, i21 = (k1 * k6 - k0 * k7) * id, i22 = (k0 * k4 - k1 * k3) * id;

    float p0 = u  * (float)W_OUT;
    float p1 = vv * (float)H_OUT;

    float cx = (i00 * p0 + i01 * p1 + i02) * d;
    float cy = (i10 * p0 + i11 * p1 + i12) * d;
    float cz = (i20 * p0 + i21 * p1 + i22) * d;

    float qx = Rm[0] * cx + Rm[1] * cy + Rm[2] * cz + tm[0];
    float qy = Rm[3] * cx + Rm[4] * cy + Rm[5] * cz + tm[1];
    float qz = Rm[6] * cx + Rm[7] * cy + Rm[8] * cz + tm[2];

    float izd = __fdividef(1.0f, qz + EPS_V);
    float ppx = qx * izd;
    float ppy = qy * izd;

    float s0 = k0 * ppx + k1 * ppy + k2;
    float s1 = k3 * ppx + k4 * ppy + k5;

    float u2 = fminf(fmaxf(s0 * (1.0f / (float)W_OUT), 0.0f), 1.0f);
    float v2 = fminf(fmaxf(s1 * (1.0f / (float)H_OUT), 0.0f), 1.0f);

    float X = (u2 * (float)W_OUT) / (float)S_RAS * 2.0f - 1.0f;
    float Y = (v2 * (float)H_OUT) / (float)S_RAS * 2.0f - 1.0f;
    float rz = __fdividef(1.0f, qz);

    g_vt[i] = make_float4(X, Y, rz, 0.0f);
}

// ---------------------------------------------------------------------------
// 1b) per-face edge setup (gathers from L2-resident g_vt)
//     w0 = A0*px + B0*py + C0 ; w1 likewise ; iz = (Az*px + Cz) + Bz*py
// ---------------------------------------------------------------------------
__global__ void __launch_bounds__(128) face_kernel(const int* __restrict__ faces)
{
    int f = blockIdx.x * blockDim.x + threadIdx.x;
    if (f >= M_F) return;

    int i0 = faces[3 * f + 0];
    int i1 = faces[3 * f + 1];
    int i2 = faces[3 * f + 2];
    pdl_wait();                 // g_vt ready

    float4 v0 = g_vt[i0];
    float4 v1 = g_vt[i1];
    float4 v2 = g_vt[i2];

    float y12 = v1.y - v2.y;
    float x21 = v2.x - v1.x;
    float y20 = v2.y - v0.y;
    float x02 = v0.x - v2.x;

    float denom = y12 * (v0.x - v2.x) + x21 * (v0.y - v2.y);
    bool  ok    = fabsf(denom) > 1e-10f;
    float inv   = __fdividef(1.0f, ok ? denom : 1.0f);

    float A0 = y12 * inv, B0 = x21 * inv;
    float A1 = y20 * inv, B1 = x02 * inv;
    float C0 = -(A0 * v2.x + B0 * v2.y);
    float C1 = -(A1 * v2.x + B1 * v2.y);

    float dr0 = v0.z - v2.z, dr1 = v1.z - v2.z;
    float Az = A0 * dr0 + A1 * dr1;
    float Bz = B0 * dr0 + B1 * dr1;
    float Cz = C0 * dr0 + C1 * dr1 + v2.z;

    g_p[f] = make_float4(A0, A1, B0, B1);
    g_q[f] = make_float4(C0, C1, Az, Bz);
    g_r[f] = Cz;

    float xmn = fminf(v0.x, fminf(v1.x, v2.x));
    float xmx = fmaxf(v0.x, fmaxf(v1.x, v2.x));
    float ymn = fminf(v0.y, fminf(v1.y, v2.y));
    float ymx = fmaxf(v0.y, fmaxf(v1.y, v2.y));
    float nanv = __int_as_float(0x7fc00000);
    g_bb[f] = ok ? make_float4(xmn, xmx, ymn, ymx)
                 : make_float4(nanv, nanv, nanv, nanv);
}

// ---------------------------------------------------------------------------
// 2) tiled raster: block = (tileX, tileY, face-segment). 32x8-px tile,
//    256 threads (1 px/thread), 1024 faces/segment in ONE smem pass.
//    Cull -> compact -> packed-FFMA2 branchless sweep.
// ---------------------------------------------------------------------------
__global__ void __launch_bounds__(NTHR) raster_kernel()
{
    __shared__ float4 sP[MSEG];     // (A0,A1,B0,B1)
    __shared__ float4 sQ[MSEG];     // (C0,C1,Az,Bz)
    __shared__ float  sR[MSEG];     // Cz
    __shared__ int    s_cnt;

    const int tX = blockIdx.x, tY = blockIdx.y, seg = blockIdx.z;
    const int t  = threadIdx.x;
    if (t == 0) s_cnt = 0;

    // tile pixel-center bounds in ndc (py decreases with row index)
    const int c0t = tX * TILE_W, r0t = tY * TILE_H;
    const float x_lo = (2.0f * c0t + 1.0f - S_RAS) / (float)S_RAS;
    const float x_hi = (2.0f * (c0t + TILE_W - 1) + 1.0f - S_RAS) / (float)S_RAS;
    const float y_hi = (float)(S_RAS - 1 - 2 * r0t) / (float)S_RAS;
    const float y_lo = (float)(S_RAS - 1 - 2 * (r0t + TILE_H - 1)) / (float)S_RAS;
    const float ctx = 0.5f * (x_lo + x_hi), cty = 0.5f * (y_lo + y_hi);
    const float hx  = 0.5f * (x_hi - x_lo), hy  = 0.5f * (y_hi - y_lo);

    // this thread's pixel
    const int r = r0t + (t >> 5);
    const int c = c0t + (t & 31);
    const float py = (float)(S_RAS - 1 - 2 * r) / (float)S_RAS;
    const float px = (2.0f * c + 1.0f - S_RAS) / (float)S_RAS;

    const unsigned long long pxDup = packf2(px, px);
    const unsigned long long pyDup = packf2(py, py);
    const unsigned long long pxpy  = packf2(px, py);

    __syncthreads();               // s_cnt visible
    pdl_wait();                    // face data ready

    // cull + compact: 1024 faces, 4 per thread
    #pragma unroll
    for (int k = 0; k < MSEG / NTHR; k++) {
        int f = seg * MSEG + k * NTHR + t;
        float4 bb = g_bb[f];
        bool ov = (bb.x <= x_hi + CULL_EPS) && (bb.y >= x_lo - CULL_EPS) &&
                  (bb.z <= y_hi + CULL_EPS) && (bb.w >= y_lo - CULL_EPS);
        if (ov) {
            float4 p = g_p[f];      // (A0,A1,B0,B1)
            float4 q = g_q[f];      // (C0,C1,Az,Bz)
            // exact max of each barycentric over the tile rect
            float w0c = p.x * ctx + p.z * cty + q.x;
            float w1c = p.y * ctx + p.w * cty + q.y;
            float b0m = w0c + fabsf(p.x) * hx + fabsf(p.z) * hy;
            float b1m = w1c + fabsf(p.y) * hx + fabsf(p.w) * hy;
            float sa  = p.x + p.y, sb = p.z + p.w;
            float b2m = 1.0f - (w0c + w1c) + fabsf(sa) * hx + fabsf(sb) * hy;
            if (b0m >= -CULL_EPS && b1m >= -CULL_EPS && b2m >= -CULL_EPS) {
                int slot = atomicAdd(&s_cnt, 1);
                sP[slot] = p;
                sQ[slot] = q;
                sR[slot] = g_r[f];
            }
        }
    }
    __syncthreads();
    const int cnt = s_cnt;

    float m = 0.0f;                // max inv_z (all inside faces have iz > 0)

    #pragma unroll 4
    for (int i = 0; i < cnt; i++) {
        const ulonglong2 P = *reinterpret_cast<const ulonglong2*>(&sP[i]); // (A0A1, B0B1)
        const ulonglong2 Q = *reinterpret_cast<const ulonglong2*>(&sQ[i]); // (C0C1, AzBz)
        const float      Cz = sR[i];

        unsigned long long t01 = fma2(P.y, pyDup, Q.x);          // (B0*py+C0, B1*py+C1)
        unsigned long long w01 = fma2(P.x, pxDup, t01);          // (w0, w1)
        unsigned long long iz2 = fma2(Q.y, pxpy, packf2(Cz, 0.0f)); // (Az*px+Cz, Bz*py)

        float w0, w1, iza, izb;
        unpackf2(w01, w0, w1);
        unpackf2(iz2, iza, izb);
        float iz = iza + izb;
        float ws = w0 + w1;
        float mn = fminf(fminf(w0, w1), 1.0f - ws);
        m = fmaxf(m, (mn >= 0.0f) ? iz : 0.0f);   // branchless
    }

    if (r < H_OUT && c < W_OUT)
        g_pm[seg * NPIX + r * W_OUT + c] = m;
}

// ---------------------------------------------------------------------------
// 3) merge segments, write depth + sil (vectorized)
// ---------------------------------------------------------------------------
__global__ void finalize_kernel(float* __restrict__ out)
{
    int q = blockIdx.x * blockDim.x + threadIdx.x;    // quad index
    if (q >= NPIX / 4) return;
    pdl_wait();
    float4 a = *reinterpret_cast<const float4*>(&g_pm[4 * q]);
    float4 b = *reinterpret_cast<const float4*>(&g_pm[NPIX + 4 * q]);
    float mv[4] = { fmaxf(a.x, b.x), fmaxf(a.y, b.y),
                    fmaxf(a.z, b.z), fmaxf(a.w, b.w) };
    float4 dep, sil;
    float* dp = &dep.x; float* sp = &sil.x;
    #pragma unroll
    for (int j = 0; j < 4; j++) {
        bool hit = mv[j] > 0.0f;
        dp[j] = hit ? fminf(FAR_V, 1.0f / mv[j]) : FAR_V;
        sp[j] = hit ? 1.0f : 0.0f;
    }
    *reinterpret_cast<float4*>(&out[4 * q])        = dep;
    *reinterpret_cast<float4*>(&out[NPIX + 4 * q]) = sil;
}

// ---------------------------------------------------------------------------
extern "C" void kernel_launch(void* const* d_in, const int* in_sizes, int n_in,
                              void* d_out, int out_size)
{
    const float* verts = (const float*)d_in[0];   // [1,8192,3] f32
    const int*   faces = (const int*)  d_in[1];   // [1,2048,3] i32
    const float* Km    = (const float*)d_in[2];   // [1,3,3]
    const float* Rm    = (const float*)d_in[3];   // [1,3,3]
    const float* tm    = (const float*)d_in[4];   // [1,3,1]
    float* out = (float*)d_out;

    {
        void* args[] = { (void*)&verts, (void*)&Km, (void*)&Rm, (void*)&tm };
        launch_pdl((void*)vert_kernel, dim3(N_V / 128), dim3(128), args);
    }
    {
        void* args[] = { (void*)&faces };
        launch_pdl((void*)face_kernel, dim3(M_F / 128), dim3(128), args);
    }
    {
        void* args[] = {};
        launch_pdl((void*)raster_kernel, dim3(TILES_X, TILES_Y, NSEG), dim3(NTHR), args);
    }
    {
        void* args[] = { (void*)&out };
        launch_pdl((void*)finalize_kernel, dim3((NPIX / 4 + 127) / 128), dim3(128), args);
    }
}

// round 15
// speedup vs baseline: 1.0654x; 1.0654x over previous
#include <cuda_runtime.h>
#include <cuda_bf16.h>

#define H_OUT 228
#define W_OUT 304
#define S_RAS 304
#define N_V   8192
#define M_F   2048
#define NSEG  4
#define MSEG  (M_F / NSEG)        // 512 faces per segment, one smem pass
#define TILE_W 32
#define TILE_H 16
#define TILES_X 10                // ceil(304/32)
#define TILES_Y 15                // ceil(228/16) -> 240 rows
#define NTHR   256                // 2 px per thread (row pair)
#define NPIX  (H_OUT * W_OUT)     // 69312 (divisible by 4)
#define FAR_V 100.0f
#define EPS_V 1e-7f
#define CULL_EPS 1e-4f

// scratch (no allocations allowed)
__device__ float4 g_vt[N_V];              // per-vertex (X, Y, 1/z, 0)
__device__ float4 g_f0[M_F];              // (A0, A1, B0, B1)
__device__ float4 g_f1[M_F];              // (C0, C1, A2, Az)
__device__ float4 g_f2[M_F];              // (B2, Bz, C2, Cz)
__device__ float4 g_bb[M_F];              // (xmin, xmax, ymin, ymax); NaN if degenerate
__device__ float  g_pm[NSEG * NPIX];      // per-segment max inv_z (every slot written)

__device__ __forceinline__ void pdl_wait() {
    asm volatile("griddepcontrol.wait;" ::: "memory");
}
__device__ __forceinline__ unsigned long long packf2(float lo, float hi) {
    unsigned long long r;
    asm("mov.b64 %0, {%1,%2};" : "=l"(r) : "f"(lo), "f"(hi));
    return r;
}
__device__ __forceinline__ unsigned long long fma2(unsigned long long a,
                                                   unsigned long long b,
                                                   unsigned long long c) {
    unsigned long long d;
    asm("fma.rn.f32x2 %0, %1, %2, %3;" : "=l"(d) : "l"(a), "l"(b), "l"(c));
    return d;
}
__device__ __forceinline__ void unpackf2(unsigned long long v, float& lo, float& hi) {
    asm("mov.b64 {%0,%1}, %2;" : "=f"(lo), "=f"(hi) : "l"(v));
}

static void launch_pdl(void* fn, dim3 grid, dim3 block, void** args) {
    cudaLaunchAttribute attr[1];
    attr[0].id = cudaLaunchAttributeProgrammaticStreamSerialization;
    attr[0].val.programmaticStreamSerializationAllowed = 1;
    cudaLaunchConfig_t cfg = {};
    cfg.gridDim = grid; cfg.blockDim = block;
    cfg.attrs = attr; cfg.numAttrs = 1;
    cudaLaunchKernelExC(&cfg, fn, args);
}

// ---------------------------------------------------------------------------
// 1a) per-vertex transform: coalesced loads, short chain
// ---------------------------------------------------------------------------
__global__ void __launch_bounds__(128) vert_kernel(const float* __restrict__ verts,
                                                   const float* __restrict__ Km,
                                                   const float* __restrict__ Rm,
                                                   const float* __restrict__ tm)
{
    int i = blockIdx.x * blockDim.x + threadIdx.x;
    if (i >= N_V) return;

    float u  = verts[3 * i + 0];
    float vv = verts[3 * i + 1];
    float d  = verts[3 * i + 2];

    float k0 = Km[0], k1 = Km[1], k2 = Km[2];
    float k3 = Km[3], k4 = Km[4], k5 = Km[5];
    float k6 = Km[6], k7 = Km[7], k8 = Km[8];

    // adjugate inverse of K
    float c00 = k4 * k8 - k5 * k7;
    float c01 = k5 * k6 - k3 * k8;
    float c02 = k3 * k7 - k4 * k6;
    float det = k0 * c00 + k1 * c01 + k2 * c02;
    float id  = __fdividef(1.0f, det);
    float i00 = c00 * id, i01 = (k2 * k7 - k1 * k8) * id, i02 = (k1 * k5 - k2 * k4) * id;
    float i10 = c01 * id, i11 = (k0 * k8 - k2 * k6) * id, i12 = (k2 * k3 - k0 * k5) * id;
    float i20 = c02 * id, i21 = (k1 * k6 - k0 * k7) * id, i22 = (k0 * k4 - k1 * k3) * id;

    float p0 = u  * (float)W_OUT;
    float p1 = vv * (float)H_OUT;

    float cx = (i00 * p0 + i01 * p1 + i02) * d;
    float cy = (i10 * p0 + i11 * p1 + i12) * d;
    float cz = (i20 * p0 + i21 * p1 + i22) * d;

    float qx = Rm[0] * cx + Rm[1] * cy + Rm[2] * cz + tm[0];
    float qy = Rm[3] * cx + Rm[4] * cy + Rm[5] * cz + tm[1];
    float qz = Rm[6] * cx + Rm[7] * cy + Rm[8] * cz + tm[2];

    float izd = __fdividef(1.0f, qz + EPS_V);
    float ppx = qx * izd;
    float ppy = qy * izd;

    float s0 = k0 * ppx + k1 * ppy + k2;
    float s1 = k3 * ppx + k4 * ppy + k5;

    float u2 = fminf(fmaxf(s0 * (1.0f / (float)W_OUT), 0.0f), 1.0f);
    float v2 = fminf(fmaxf(s1 * (1.0f / (float)H_OUT), 0.0f), 1.0f);

    float X = (u2 * (float)W_OUT) / (float)S_RAS * 2.0f - 1.0f;
    float Y = (v2 * (float)H_OUT) / (float)S_RAS * 2.0f - 1.0f;
    float rz = __fdividef(1.0f, qz);

    g_vt[i] = make_float4(X, Y, rz, 0.0f);
}

// ---------------------------------------------------------------------------
// 1b) per-face edge setup (gathers from L2-resident g_vt)
//     w_k = Ak*px + Bk*py + Ck (k=0,1,2) ; iz = Az*px + Bz*py + Cz
// ---------------------------------------------------------------------------
__global__ void __launch_bounds__(128) face_kernel(const int* __restrict__ faces)
{
    int f = blockIdx.x * blockDim.x + threadIdx.x;
    if (f >= M_F) return;

    int i0 = faces[3 * f + 0];
    int i1 = faces[3 * f + 1];
    int i2 = faces[3 * f + 2];
    pdl_wait();                 // g_vt ready

    float4 v0 = g_vt[i0];
    float4 v1 = g_vt[i1];
    float4 v2 = g_vt[i2];

    float y12 = v1.y - v2.y;
    float x21 = v2.x - v1.x;
    float y20 = v2.y - v0.y;
    float x02 = v0.x - v2.x;

    float denom = y12 * (v0.x - v2.x) + x21 * (v0.y - v2.y);
    bool  ok    = fabsf(denom) > 1e-10f;
    float inv   = __fdividef(1.0f, ok ? denom : 1.0f);

    float A0 = y12 * inv, B0 = x21 * inv;
    float A1 = y20 * inv, B1 = x02 * inv;
    float C0 = -(A0 * v2.x + B0 * v2.y);
    float C1 = -(A1 * v2.x + B1 * v2.y);
    float A2 = -(A0 + A1), B2 = -(B0 + B1), C2 = 1.0f - C0 - C1;

    float dr0 = v0.z - v2.z, dr1 = v1.z - v2.z;
    float Az = A0 * dr0 + A1 * dr1;
    float Bz = B0 * dr0 + B1 * dr1;
    float Cz = C0 * dr0 + C1 * dr1 + v2.z;

    g_f0[f] = make_float4(A0, A1, B0, B1);
    g_f1[f] = make_float4(C0, C1, A2, Az);
    g_f2[f] = make_float4(B2, Bz, C2, Cz);

    float xmn = fminf(v0.x, fminf(v1.x, v2.x));
    float xmx = fmaxf(v0.x, fmaxf(v1.x, v2.x));
    float ymn = fminf(v0.y, fminf(v1.y, v2.y));
    float ymx = fmaxf(v0.y, fmaxf(v1.y, v2.y));
    float nanv = __int_as_float(0x7fc00000);
    g_bb[f] = ok ? make_float4(xmn, xmx, ymn, ymx)
                 : make_float4(nanv, nanv, nanv, nanv);
}

// ---------------------------------------------------------------------------
// 2) tiled raster: block = (tileX, tileY, face-segment). 32x16-px tile,
//    256 threads, 2 row-paired px/thread, 512 faces/segment in one pass.
//    Pair-packed sweep: (w0,w1) and (w2,iz) via fma2; the px-dependent
//    inner fma2 is shared across the two rows.
// ---------------------------------------------------------------------------
__global__ void __launch_bounds__(NTHR) raster_kernel()
{
    __shared__ float4 s0[MSEG];     // (A0,A1,B0,B1)
    __shared__ float4 s1[MSEG];     // (C0,C1,A2,Az)
    __shared__ float4 s2[MSEG];     // (B2,Bz,C2,Cz)
    __shared__ int    s_cnt;

    const int tX = blockIdx.x, tY = blockIdx.y, seg = blockIdx.z;
    const int t  = threadIdx.x;
    if (t == 0) s_cnt = 0;

    // tile pixel-center bounds in ndc (py decreases with row index)
    const int c0t = tX * TILE_W, r0t = tY * TILE_H;
    const float x_lo = (2.0f * c0t + 1.0f - S_RAS) / (float)S_RAS;
    const float x_hi = (2.0f * (c0t + TILE_W - 1) + 1.0f - S_RAS) / (float)S_RAS;
    const float y_hi = (float)(S_RAS - 1 - 2 * r0t) / (float)S_RAS;
    const float y_lo = (float)(S_RAS - 1 - 2 * (r0t + TILE_H - 1)) / (float)S_RAS;
    const float ctx = 0.5f * (x_lo + x_hi), cty = 0.5f * (y_lo + y_hi);
    const float hx  = 0.5f * (x_hi - x_lo), hy  = 0.5f * (y_hi - y_lo);

    // this thread's 2 pixels: rows r0,r0+1, column c
    const int r0 = r0t + 2 * (t >> 5);
    const int c  = c0t + (t & 31);
    const float py0 = (float)(S_RAS - 1 - 2 * r0) / (float)S_RAS;
    const float py1 = (float)(S_RAS - 3 - 2 * r0) / (float)S_RAS;
    const float px  = (2.0f * c + 1.0f - S_RAS) / (float)S_RAS;

    const unsigned long long pxDup  = packf2(px,  px);
    const unsigned long long py0Dup = packf2(py0, py0);
    const unsigned long long py1Dup = packf2(py1, py1);

    __syncthreads();               // s_cnt visible
    pdl_wait();                    // face data ready

    // cull + compact: 512 faces, 2 per thread
    #pragma unroll
    for (int k = 0; k < MSEG / NTHR; k++) {
        int f = seg * MSEG + k * NTHR + t;
        float4 bb = g_bb[f];
        bool ov = (bb.x <= x_hi + CULL_EPS) && (bb.y >= x_lo - CULL_EPS) &&
                  (bb.z <= y_hi + CULL_EPS) && (bb.w >= y_lo - CULL_EPS);
        if (ov) {
            float4 f0 = g_f0[f];    // (A0,A1,B0,B1)
            float4 f1 = g_f1[f];    // (C0,C1,A2,Az)
            float4 f2 = g_f2[f];    // (B2,Bz,C2,Cz)
            float b0m = f0.x * ctx + f0.z * cty + f1.x + fabsf(f0.x) * hx + fabsf(f0.z) * hy;
            float b1m = f0.y * ctx + f0.w * cty + f1.y + fabsf(f0.y) * hx + fabsf(f0.w) * hy;
            float b2m = f1.z * ctx + f2.x * cty + f2.z + fabsf(f1.z) * hx + fabsf(f2.x) * hy;
            if (b0m >= -CULL_EPS && b1m >= -CULL_EPS && b2m >= -CULL_EPS) {
                int slot = atomicAdd(&s_cnt, 1);
                s0[slot] = f0;
                s1[slot] = f1;
                s2[slot] = f2;
            }
        }
    }
    __syncthreads();
    const int cnt = s_cnt;

    float m0 = 0.0f, m1 = 0.0f;    // max inv_z per row (inside faces: iz > 0)

    #pragma unroll 4
    for (int i = 0; i < cnt; i++) {
        const ulonglong2 F0 = *reinterpret_cast<const ulonglong2*>(&s0[i]); // (A0A1, B0B1)
        const ulonglong2 F1 = *reinterpret_cast<const ulonglong2*>(&s1[i]); // (C0C1, A2Az)
        const ulonglong2 F2 = *reinterpret_cast<const ulonglong2*>(&s2[i]); // (B2Bz, C2Cz)

        // px-dependent terms shared across both rows
        unsigned long long sw = fma2(F0.x, pxDup, F1.x);   // (A0*px+C0, A1*px+C1)
        unsigned long long sv = fma2(F1.y, pxDup, F2.y);   // (A2*px+C2, Az*px+Cz)

        // row 0
        {
            unsigned long long w01 = fma2(F0.y, py0Dup, sw);   // (w0, w1)
            unsigned long long v2z = fma2(F2.x, py0Dup, sv);   // (w2, iz)
            float w0, w1, w2, iz;
            unpackf2(w01, w0, w1);
            unpackf2(v2z, w2, iz);
            float mn = fminf(fminf(w0, w1), w2);
            m0 = fmaxf(m0, (mn >= 0.0f) ? iz : 0.0f);
        }
        // row 1
        {
            unsigned long long w01 = fma2(F0.y, py1Dup, sw);
            unsigned long long v2z = fma2(F2.x, py1Dup, sv);
            float w0, w1, w2, iz;
            unpackf2(w01, w0, w1);
            unpackf2(v2z, w2, iz);
            float mn = fminf(fminf(w0, w1), w2);
            m1 = fmaxf(m1, (mn >= 0.0f) ? iz : 0.0f);
        }
    }

    if (c < W_OUT) {
        if (r0 < H_OUT)     g_pm[seg * NPIX + r0 * W_OUT + c]       = m0;
        if (r0 + 1 < H_OUT) g_pm[seg * NPIX + (r0 + 1) * W_OUT + c] = m1;
    }
}

// ---------------------------------------------------------------------------
// 3) merge segments, write depth + sil (vectorized)
// ---------------------------------------------------------------------------
__global__ void finalize_kernel(float* __restrict__ out)
{
    int q = blockIdx.x * blockDim.x + threadIdx.x;    // quad index
    if (q >= NPIX / 4) return;
    pdl_wait();
    float4 a = *reinterpret_cast<const float4*>(&g_pm[4 * q]);
    float mv[4] = { a.x, a.y, a.z, a.w };
    #pragma unroll
    for (int s = 1; s < NSEG; s++) {
        float4 b = *reinterpret_cast<const float4*>(&g_pm[s * NPIX + 4 * q]);
        mv[0] = fmaxf(mv[0], b.x); mv[1] = fmaxf(mv[1], b.y);
        mv[2] = fmaxf(mv[2], b.z); mv[3] = fmaxf(mv[3], b.w);
    }
    float4 dep, sil;
    float* dp = &dep.x; float* sp = &sil.x;
    #pragma unroll
    for (int j = 0; j < 4; j++) {
        bool hit = mv[j] > 0.0f;
        dp[j] = hit ? fminf(FAR_V, 1.0f / mv[j]) : FAR_V;
        sp[j] = hit ? 1.0f : 0.0f;
    }
    *reinterpret_cast<float4*>(&out[4 * q])        = dep;
    *reinterpret_cast<float4*>(&out[NPIX + 4 * q]) = sil;
}

// ---------------------------------------------------------------------------
extern "C" void kernel_launch(void* const* d_in, const int* in_sizes, int n_in,
                              void* d_out, int out_size)
{
    const float* verts = (const float*)d_in[0];   // [1,8192,3] f32
    const int*   faces = (const int*)  d_in[1];   // [1,2048,3] i32
    const float* Km    = (const float*)d_in[2];   // [1,3,3]
    const float* Rm    = (const float*)d_in[3];   // [1,3,3]
    const float* tm    = (const float*)d_in[4];   // [1,3,1]
    float* out = (float*)d_out;

    {
        void* args[] = { (void*)&verts, (void*)&Km, (void*)&Rm, (void*)&tm };
        launch_pdl((void*)vert_kernel, dim3(N_V / 128), dim3(128), args);
    }
    {
        void* args[] = { (void*)&faces };
        launch_pdl((void*)face_kernel, dim3(M_F / 128), dim3(128), args);
    }
    {
        void* args[] = {};
        launch_pdl((void*)raster_kernel, dim3(TILES_X, TILES_Y, NSEG), dim3(NTHR), args);
    }
    {
        void* args[] = { (void*)&out };
        launch_pdl((void*)finalize_kernel, dim3((NPIX / 4 + 127) / 128), dim3(128), args);
    }
}